// round 16
// baseline (speedup 1.0000x reference)
#include <cuda_runtime.h>
#include <cuda_fp16.h>
#include <cstdint>

#define B_DIM   512
#define IN_DIM  4096
#define OUT_DIM 11008

#define BM 128
#define BN 128
#define BK 32
#define NK (IN_DIM / BK)   // 128 k-chunks
#define STAGES 4
#define THREADS 256

#define ROWPAD 80                        // 64B data + 16B pad per row (bank-conflict-free)
#define TILE_B0 (BM * ROWPAD)            // A tile bytes: 10240 (B tile follows at this offset)
#define STAGE_B (2 * BM * ROWPAD)        // 20480 B per stage (A + B)
#define SM_LUT_BYTES 1024                // 512 x u16 sign-folded dequant LUT
#define SMEM_TOTAL (SM_LUT_BYTES + STAGES * STAGE_B)   // 82944 B -> 2 CTAs/SM

// ---------------- device scratch (static device arrays are allowed) ----------------
__device__ __half g_x[(size_t)B_DIM * IN_DIM];

// ---------------- PTX helpers (plain sm_80+ features only) -------------------------
__device__ __forceinline__ uint32_t smem_u32(const void* p) {
    uint32_t a;
    asm("{ .reg .u64 t; cvta.to.shared.u64 t, %1; cvt.u32.u64 %0, t; }" : "=r"(a) : "l"(p));
    return a;
}

__device__ __forceinline__ void cp16(uint32_t s, const void* g) {
    asm volatile("cp.async.cg.shared.global [%0], [%1], 16;" :: "r"(s), "l"(g));
}
__device__ __forceinline__ void cp_commit() {
    asm volatile("cp.async.commit_group;" ::: "memory");
}
template <int N>
__device__ __forceinline__ void cp_wait() {
    asm volatile("cp.async.wait_group %0;" :: "n"(N) : "memory");
}

__device__ __forceinline__ void ldsm4(uint32_t* r, uint32_t addr) {
    asm volatile("ldmatrix.sync.aligned.m8n8.x4.shared.b16 {%0,%1,%2,%3}, [%4];"
                 : "=r"(r[0]), "=r"(r[1]), "=r"(r[2]), "=r"(r[3]) : "r"(addr));
}

__device__ __forceinline__ void mma_fp16(float* d, const uint32_t* a, const uint32_t* b) {
    asm volatile("mma.sync.aligned.m16n8k16.row.col.f32.f16.f16.f32 "
                 "{%0,%1,%2,%3}, {%4,%5,%6,%7}, {%8,%9}, {%0,%1,%2,%3};"
                 : "+f"(d[0]), "+f"(d[1]), "+f"(d[2]), "+f"(d[3])
                 : "r"(a[0]), "r"(a[1]), "r"(a[2]), "r"(a[3]), "r"(b[0]), "r"(b[1]));
}

// ---------------- Kernel 1: convert x -> fp16 --------------------------------------
__global__ void xconv_kernel(const float* __restrict__ x) {
    const float4* x4 = (const float4*)x;
    ushort4* xh = (ushort4*)g_x;
    size_t n4 = (size_t)B_DIM * IN_DIM / 4;
    for (size_t i = (size_t)blockIdx.x * blockDim.x + threadIdx.x; i < n4;
         i += (size_t)gridDim.x * blockDim.x) {
        float4 v = x4[i];
        xh[i] = make_ushort4(__half_as_ushort(__float2half_rn(v.x)),
                             __half_as_ushort(__float2half_rn(v.y)),
                             __half_as_ushort(__float2half_rn(v.z)),
                             __half_as_ushort(__float2half_rn(v.w)));
    }
}

// ---------------- Kernel 2: FUSED dequant + pipelined mma.sync fp16 GEMM -----------
// B-producer reads stored/sign int32 directly, dequants through a 512-entry
// sign-folded LUT (identical fp16 values to the old dequant kernel), and stores
// fp16 tiles to smem. Grid (M=4, N=86): the 4 CTAs sharing an N-block are
// adjacent bids -> co-resident -> stored/sign 4x-reused out of L2.
__global__ void __launch_bounds__(THREADS, 2)
gemm_fused_kernel(float* __restrict__ out, const float* __restrict__ scale,
                  const float* __restrict__ bias,
                  const int* __restrict__ stored, const int* __restrict__ sgn,
                  const float* __restrict__ lmin_p, const float* __restrict__ lmax_p) {
    extern __shared__ char smem[];
    unsigned short* lut = (unsigned short*)smem;
    const uint32_t sb = smem_u32(smem) + SM_LUT_BYTES;   // stage base
    const int tid = threadIdx.x;
    const int lane = tid & 31, wid = tid >> 5;
    const int mb = blockIdx.x * BM, nb = blockIdx.y * BN;
    const int warp_m = (wid & 3) * 32, warp_n = (wid >> 2) * 64;

    // Build sign-folded dequant LUT: idx = stored | (neg << 8)
    {
        float lmin = *lmin_p;
        float kf = (*lmax_p - lmin) * (1.0f / 254.0f);
#pragma unroll
        for (int i = 0; i < 2; i++) {
            int s = tid + i * THREADS;               // 0..511
            float w = expf(lmin + (float)(255 - (s & 255)) * kf);
            unsigned short hb = __half_as_ushort(__float2half_rn(w));
            lut[s] = hb ^ ((s >> 8) ? 0x8000u : 0u);
        }
    }
    __syncthreads();

    const char* gA = (const char*)(g_x + (size_t)mb * IN_DIM);
    const int* gst = stored + (size_t)nb * IN_DIM;
    const int* gsg = sgn + (size_t)nb * IN_DIM;

    // A cp.async mapping: thread -> (row = tid/2, 32B half = tid%2)
    const int lrow = tid >> 1;
    const int lc = (tid & 1) * 32;

    // B producer mapping: per half (16 k-cols = 4 int4 chunks/row), 512 chunks,
    // 2 per thread: idx = p*256 + tid -> row = idx>>2, c4 = idx&3 (coalesced).
    const int brow0 = tid >> 2;          // p=0 row
    const int bc4 = (tid & 3);           // int4 index within half

    // ldmatrix base offsets
    const uint32_t a_off = (uint32_t)(warp_m + (lane & 15)) * ROWPAD + ((lane >> 4) * 16);
    const uint32_t b_off =
        (uint32_t)(warp_n + (lane & 7) + ((lane >> 4) & 1) * 8) * ROWPAD + (((lane >> 3) & 1) * 16);

    float acc[2][8][4];
#pragma unroll
    for (int i = 0; i < 2; i++)
#pragma unroll
        for (int j = 0; j < 8; j++)
#pragma unroll
            for (int c = 0; c < 4; c++) acc[i][j][c] = 0.0f;

    // ---- producer helpers ----
    auto load_A = [&](int s, int k) {
        size_t go = (size_t)lrow * (IN_DIM * 2) + (size_t)k * (BK * 2) + lc;
        uint32_t so = sb + s * STAGE_B + (uint32_t)lrow * ROWPAD + lc;
        cp16(so, gA + go);
        cp16(so + 16, gA + go + 16);
    };

    // Load raw stored/sign int4s for one half (16 k-cols) of stage k.
    auto ldg_B_half = [&](int k, int h, int4* st, int4* sg) {
#pragma unroll
        for (int p = 0; p < 2; p++) {
            int row = brow0 + p * 64;
            size_t e = (size_t)row * IN_DIM + k * BK + h * 16 + bc4 * 4;
            st[p] = *(const int4*)(gst + e);
            sg[p] = *(const int4*)(gsg + e);
        }
    };

    // Convert + store one half into stage s.
    auto sts_B_half = [&](int s, int h, const int4* st, const int4* sg) {
#pragma unroll
        for (int p = 0; p < 2; p++) {
            int row = brow0 + p * 64;
            uint32_t i0 = (st[p].x & 255) | ((((uint32_t)sg[p].x) >> 31) << 8);
            uint32_t i1 = (st[p].y & 255) | ((((uint32_t)sg[p].y) >> 31) << 8);
            uint32_t i2 = (st[p].z & 255) | ((((uint32_t)sg[p].z) >> 31) << 8);
            uint32_t i3 = (st[p].w & 255) | ((((uint32_t)sg[p].w) >> 31) << 8);
            uint32_t w01 = (uint32_t)lut[i0] | ((uint32_t)lut[i1] << 16);
            uint32_t w23 = (uint32_t)lut[i2] | ((uint32_t)lut[i3] << 16);
            uint32_t so = sb + s * STAGE_B + TILE_B0 + (uint32_t)row * ROWPAD + h * 32 + bc4 * 8;
            asm volatile("st.shared.v2.b32 [%0], {%1, %2};" :: "r"(so), "r"(w01), "r"(w23)
                         : "memory");
        }
    };

    // ---- consumer: one s16 half (16 MMAs/warp) ----
    auto compute_half = [&](int s, int s16) {
        uint32_t st_ = sb + s * STAGE_B;
        uint32_t aA = st_ + a_off;
        uint32_t bB = st_ + TILE_B0 + b_off;
        uint32_t kb = s16 * 32;
        uint32_t a[2][4];
        ldsm4(a[0], aA + kb);
        ldsm4(a[1], aA + 16 * ROWPAD + kb);
#pragma unroll
        for (int nblk = 0; nblk < 4; nblk++) {
            uint32_t b[4];
            ldsm4(b, bB + nblk * 16 * ROWPAD + kb);
#pragma unroll
            for (int mt = 0; mt < 2; mt++) {
                mma_fp16(acc[mt][2 * nblk], a[mt], b);
                mma_fp16(acc[mt][2 * nblk + 1], a[mt], b + 2);
            }
        }
    };

    // ---- prologue: fill STAGES-1 stages (synchronous B convert is fine here) ----
#pragma unroll
    for (int s = 0; s < STAGES - 1; s++) {
        int4 st0[2], sg0[2];
        ldg_B_half(s, 0, st0, sg0);
        sts_B_half(s, 0, st0, sg0);
        ldg_B_half(s, 1, st0, sg0);
        sts_B_half(s, 1, st0, sg0);
        load_A(s, s);
        cp_commit();
    }

    int rs = 0, ws = STAGES - 1;
    for (int k = 0; k < NK; k++) {
        cp_wait<STAGES - 2>();
        __syncthreads();
        const int kl = k + STAGES - 1;
        const bool hasNext = kl < NK;
        int4 st0[2], sg0[2];
        if (hasNext) ldg_B_half(kl, 0, st0, sg0);       // LDG latency hides under MMAs
        compute_half(rs, 0);
        if (hasNext) {
            sts_B_half(ws, 0, st0, sg0);
            ldg_B_half(kl, 1, st0, sg0);
        }
        compute_half(rs, 1);
        if (hasNext) {
            sts_B_half(ws, 1, st0, sg0);
            load_A(ws, kl);
        }
        cp_commit();
        rs = (rs + 1) & (STAGES - 1);
        ws = (ws + 1) & (STAGES - 1);
    }

    // epilogue: (acc + bias) * scale, float2 stores
#pragma unroll
    for (int nf = 0; nf < 8; nf++) {
        int n0 = nb + warp_n + nf * 8 + 2 * (lane & 3);
        float s0 = scale[n0], s1 = scale[n0 + 1];
        float b0 = bias[n0], b1 = bias[n0 + 1];
#pragma unroll
        for (int mt = 0; mt < 2; mt++) {
            int m0 = mb + warp_m + mt * 16 + (lane >> 2);
            float* p0 = out + (size_t)m0 * OUT_DIM + n0;
            float2 v0;
            v0.x = (acc[mt][nf][0] + b0) * s0;
            v0.y = (acc[mt][nf][1] + b1) * s1;
            *(float2*)p0 = v0;
            float2 v1;
            v1.x = (acc[mt][nf][2] + b0) * s0;
            v1.y = (acc[mt][nf][3] + b1) * s1;
            *(float2*)(p0 + 8 * OUT_DIM) = v1;
        }
    }
}

// ---------------- launch ----------------
extern "C" void kernel_launch(void* const* d_in, const int* in_sizes, int n_in,
                              void* d_out, int out_size) {
    const float* x      = (const float*)d_in[0];
    const int*   stored = (const int*)d_in[1];
    const int*   sgn    = (const int*)d_in[2];
    const float* lmin   = (const float*)d_in[3];
    const float* lmax   = (const float*)d_in[4];
    const float* scale  = (const float*)d_in[5];
    const float* bias   = (const float*)d_in[6];
    float* out = (float*)d_out;

    xconv_kernel<<<512, 256>>>(x);

    static int smem_set = 0;
    if (!smem_set) {
        cudaFuncSetAttribute(gemm_fused_kernel, cudaFuncAttributeMaxDynamicSharedMemorySize,
                             SMEM_TOTAL);
        smem_set = 1;
    }
    dim3 grid(B_DIM / BM, OUT_DIM / BN);   // (4, 86): M fastest -> N-block CTAs adjacent
    gemm_fused_kernel<<<grid, THREADS, SMEM_TOTAL>>>(out, scale, bias, stored, sgn, lmin, lmax);
}

// round 17
// speedup vs baseline: 2.1857x; 2.1857x over previous
#include <cuda_runtime.h>
#include <cuda_fp16.h>
#include <cstdint>

#define B_DIM   512
#define IN_DIM  4096
#define OUT_DIM 11008

#define BM 64
#define BN 128
#define BK 32
#define NK (IN_DIM / BK)   // 128 k-chunks
#define STAGES 4
#define THREADS 128

#define ROWB 64                          // 64B per row (no pad; XOR swizzle instead)
#define TILE_A_B (BM * ROWB)             // 4096 B
#define TILE_B_B (BN * ROWB)             // 8192 B
#define STAGE_B (TILE_A_B + TILE_B_B)    // 12288 B per stage
#define SMEM_TOTAL (STAGES * STAGE_B)    // 49152 B -> 4 CTAs/SM = 192KB

// XOR swizzle of the 16B-chunk index within a 64B row:
// chunk' = chunk ^ (row&3) ^ ((row>>2)&3). Rows +16 leave it invariant.
__device__ __forceinline__ uint32_t swz_mask(int row) {
    return (uint32_t)((row & 3) ^ ((row >> 2) & 3));
}

// ---------------- device scratch (static device arrays are allowed) ----------------
__device__ __half g_w[(size_t)OUT_DIM * IN_DIM];
__device__ __half g_x[(size_t)B_DIM * IN_DIM];

// ---------------- PTX helpers (plain sm_80+ features only) -------------------------
__device__ __forceinline__ uint32_t smem_u32(const void* p) {
    uint32_t a;
    asm("{ .reg .u64 t; cvta.to.shared.u64 t, %1; cvt.u32.u64 %0, t; }" : "=r"(a) : "l"(p));
    return a;
}

__device__ __forceinline__ void cp16(uint32_t s, const void* g) {
    asm volatile("cp.async.cg.shared.global [%0], [%1], 16;" :: "r"(s), "l"(g));
}
__device__ __forceinline__ void cp_commit() {
    asm volatile("cp.async.commit_group;" ::: "memory");
}
template <int N>
__device__ __forceinline__ void cp_wait() {
    asm volatile("cp.async.wait_group %0;" :: "n"(N) : "memory");
}

__device__ __forceinline__ void ldsm4(uint32_t* r, uint32_t addr) {
    asm volatile("ldmatrix.sync.aligned.m8n8.x4.shared.b16 {%0,%1,%2,%3}, [%4];"
                 : "=r"(r[0]), "=r"(r[1]), "=r"(r[2]), "=r"(r[3]) : "r"(addr));
}

__device__ __forceinline__ void mma_fp16(float* d, const uint32_t* a, const uint32_t* b) {
    asm volatile("mma.sync.aligned.m16n8k16.row.col.f32.f16.f16.f32 "
                 "{%0,%1,%2,%3}, {%4,%5,%6,%7}, {%8,%9}, {%0,%1,%2,%3};"
                 : "+f"(d[0]), "+f"(d[1]), "+f"(d[2]), "+f"(d[3])
                 : "r"(a[0]), "r"(a[1]), "r"(a[2]), "r"(a[3]), "r"(b[0]), "r"(b[1]));
}

// ---------------- Kernel 1: dequant W -> single fp16 (256-entry exp LUT) -----------
__global__ void dequant_kernel(const int* __restrict__ stored, const int* __restrict__ sgn,
                               const float* __restrict__ lmin_p, const float* __restrict__ lmax_p) {
    __shared__ unsigned short lut[256];
    float lmin = *lmin_p;
    float kf = (*lmax_p - lmin) * (1.0f / 254.0f);
    for (int s = threadIdx.x; s < 256; s += blockDim.x) {
        float w = expf(lmin + (float)(255 - s) * kf);
        lut[s] = __half_as_ushort(__float2half_rn(w));
    }
    __syncthreads();

    const int4* st4 = (const int4*)stored;
    const int4* sg4 = (const int4*)sgn;
    ushort4* w4 = (ushort4*)g_w;
    size_t nq = (size_t)OUT_DIM * IN_DIM / 4;
    for (size_t i = (size_t)blockIdx.x * blockDim.x + threadIdx.x; i < nq;
         i += (size_t)gridDim.x * blockDim.x) {
        int4 s = st4[i];
        int4 g = sg4[i];
        unsigned short h0 = lut[s.x & 255] ^ (g.x < 0 ? 0x8000u : 0u);
        unsigned short h1 = lut[s.y & 255] ^ (g.y < 0 ? 0x8000u : 0u);
        unsigned short h2 = lut[s.z & 255] ^ (g.z < 0 ? 0x8000u : 0u);
        unsigned short h3 = lut[s.w & 255] ^ (g.w < 0 ? 0x8000u : 0u);
        w4[i] = make_ushort4(h0, h1, h2, h3);
    }
}

// ---------------- Kernel 2: convert x -> fp16 --------------------------------------
__global__ void xconv_kernel(const float* __restrict__ x) {
    const float4* x4 = (const float4*)x;
    ushort4* xh = (ushort4*)g_x;
    size_t n4 = (size_t)B_DIM * IN_DIM / 4;
    for (size_t i = (size_t)blockIdx.x * blockDim.x + threadIdx.x; i < n4;
         i += (size_t)gridDim.x * blockDim.x) {
        float4 v = x4[i];
        xh[i] = make_ushort4(__half_as_ushort(__float2half_rn(v.x)),
                             __half_as_ushort(__float2half_rn(v.y)),
                             __half_as_ushort(__float2half_rn(v.z)),
                             __half_as_ushort(__float2half_rn(v.w)));
    }
}

// ---------------- Kernel 3: pipelined mma.sync fp16 GEMM + epilogue ----------------
// BM=64 / 128 threads / 4 warps (2 along M x 2 along N, 32x64 warp tiles).
// XOR-swizzled 64B smem rows -> 12KB stages -> 4 CTAs/SM co-resident.
__global__ void __launch_bounds__(THREADS, 4)
gemm_kernel(float* __restrict__ out, const float* __restrict__ scale,
            const float* __restrict__ bias) {
    extern __shared__ char smem[];
    const uint32_t sb = smem_u32(smem);
    const int tid = threadIdx.x;
    const int lane = tid & 31, wid = tid >> 5;
    const int nb = blockIdx.x * BN, mb = blockIdx.y * BM;
    const int warp_m = (wid & 1) * 32, warp_n = (wid >> 1) * 64;

    const char* gA = (const char*)(g_x + (size_t)mb * IN_DIM);
    const char* gB = (const char*)(g_w + (size_t)nb * IN_DIM);

    // ldmatrix per-thread row geometry (+ precomputed swizzle masks)
    const int a_row = warp_m + (lane & 15);
    const uint32_t a_rowoff = (uint32_t)a_row * ROWB;
    const uint32_t a_swm = swz_mask(a_row);
    const uint32_t a_ch = (uint32_t)(lane >> 4);          // logical chunk half

    const int b_row = warp_n + (lane & 7) + ((lane >> 4) & 1) * 8;
    const uint32_t b_rowoff = (uint32_t)b_row * ROWB;
    const uint32_t b_swm = swz_mask(b_row);
    const uint32_t b_ch = (uint32_t)((lane >> 3) & 1);

    float acc[2][8][4];
#pragma unroll
    for (int i = 0; i < 2; i++)
#pragma unroll
        for (int j = 0; j < 8; j++)
#pragma unroll
            for (int c = 0; c < 4; c++) acc[i][j][c] = 0.0f;

    // cp.async producer: chunk idx -> (row = idx>>2, c = idx&3), swizzled store.
    // A: 256 chunks (2/thread), B: 512 chunks (4/thread). Coalesced on global side.
    auto load_stage = [&](int s, int k) {
        uint32_t st = sb + s * STAGE_B;
        size_t kbyte = (size_t)k * (BK * 2);
#pragma unroll
        for (int i = 0; i < 2; i++) {
            int idx = tid + i * THREADS;          // 0..255
            int row = idx >> 2, c = idx & 3;
            uint32_t cs = (uint32_t)c ^ swz_mask(row);
            cp16(st + (uint32_t)row * ROWB + cs * 16,
                 gA + (size_t)row * (IN_DIM * 2) + kbyte + c * 16);
        }
#pragma unroll
        for (int i = 0; i < 4; i++) {
            int idx = tid + i * THREADS;          // 0..511
            int row = idx >> 2, c = idx & 3;
            uint32_t cs = (uint32_t)c ^ swz_mask(row);
            cp16(st + TILE_A_B + (uint32_t)row * ROWB + cs * 16,
                 gB + (size_t)row * (IN_DIM * 2) + kbyte + c * 16);
        }
    };

    auto compute_stage = [&](int s) {
        uint32_t st = sb + s * STAGE_B;
#pragma unroll
        for (int s16 = 0; s16 < 2; s16++) {
            uint32_t ca = ((a_ch + 2 * s16) ^ a_swm) * 16;
            uint32_t a[2][4];
            ldsm4(a[0], st + a_rowoff + ca);
            ldsm4(a[1], st + a_rowoff + 16 * ROWB + ca);   // +16 rows: swizzle invariant
            uint32_t cb = ((b_ch + 2 * s16) ^ b_swm) * 16;
#pragma unroll
            for (int nblk = 0; nblk < 4; nblk++) {
                uint32_t b[4];
                ldsm4(b, st + TILE_A_B + b_rowoff + nblk * 16 * ROWB + cb);
#pragma unroll
                for (int mt = 0; mt < 2; mt++) {
                    mma_fp16(acc[mt][2 * nblk], a[mt], b);
                    mma_fp16(acc[mt][2 * nblk + 1], a[mt], b + 2);
                }
            }
        }
    };

    // prologue: fill STAGES-1 stages
#pragma unroll
    for (int s = 0; s < STAGES - 1; s++) {
        load_stage(s, s);
        cp_commit();
    }

    int rs = 0, ws = STAGES - 1;
    for (int k = 0; k < NK; k++) {
        cp_wait<STAGES - 2>();
        __syncthreads();
        compute_stage(rs);
        if (k + STAGES - 1 < NK) load_stage(ws, k + STAGES - 1);
        cp_commit();
        rs = (rs + 1) & (STAGES - 1);
        ws = (ws + 1) & (STAGES - 1);
    }

    // epilogue: (acc + bias) * scale, float2 stores
#pragma unroll
    for (int nf = 0; nf < 8; nf++) {
        int n0 = nb + warp_n + nf * 8 + 2 * (lane & 3);
        float s0 = scale[n0], s1 = scale[n0 + 1];
        float b0 = bias[n0], b1 = bias[n0 + 1];
#pragma unroll
        for (int mt = 0; mt < 2; mt++) {
            int m0 = mb + warp_m + mt * 16 + (lane >> 2);
            float* p0 = out + (size_t)m0 * OUT_DIM + n0;
            float2 v0;
            v0.x = (acc[mt][nf][0] + b0) * s0;
            v0.y = (acc[mt][nf][1] + b1) * s1;
            *(float2*)p0 = v0;
            float2 v1;
            v1.x = (acc[mt][nf][2] + b0) * s0;
            v1.y = (acc[mt][nf][3] + b1) * s1;
            *(float2*)(p0 + 8 * OUT_DIM) = v1;
        }
    }
}

// ---------------- launch ----------------
extern "C" void kernel_launch(void* const* d_in, const int* in_sizes, int n_in,
                              void* d_out, int out_size) {
    const float* x      = (const float*)d_in[0];
    const int*   stored = (const int*)d_in[1];
    const int*   sgn    = (const int*)d_in[2];
    const float* lmin   = (const float*)d_in[3];
    const float* lmax   = (const float*)d_in[4];
    const float* scale  = (const float*)d_in[5];
    const float* bias   = (const float*)d_in[6];
    float* out = (float*)d_out;

    dequant_kernel<<<4096, 256>>>(stored, sgn, lmin, lmax);
    xconv_kernel<<<512, 256>>>(x);

    static int smem_set = 0;
    if (!smem_set) {
        cudaFuncSetAttribute(gemm_kernel, cudaFuncAttributeMaxDynamicSharedMemorySize, SMEM_TOTAL);
        smem_set = 1;
    }
    dim3 grid(OUT_DIM / BN, B_DIM / BM);   // (86, 8)
    gemm_kernel<<<grid, THREADS, SMEM_TOTAL>>>(out, scale, bias);
}